// round 4
// baseline (speedup 1.0000x reference)
#include <cuda_runtime.h>
#include <math.h>

#define NG 512
#define IMG_H 256
#define IMG_W 256
#define EPSV 1e-4f

// Sorted gaussian params, AoS of 3 float4 per gaussian:
//  [0]: mx, my, ia, ib      (2D mean, inverse-cov 00 and 01)
//  [1]: id, coeff, colR, colG
//  [2]: colB, -, -, -
__device__ float4 g_params[NG * 3];

__global__ void project_sort_kernel(const float* __restrict__ means3D,
                                    const float* __restrict__ covs3d,
                                    const float* __restrict__ colors,
                                    const float* __restrict__ opac,
                                    const float* __restrict__ Km,
                                    const float* __restrict__ Rm,
                                    const float* __restrict__ tv) {
    __shared__ float sdepth[NG];
    int i = threadIdx.x;

    float m0 = means3D[3*i+0], m1 = means3D[3*i+1], m2 = means3D[3*i+2];

    float R00=Rm[0],R01=Rm[1],R02=Rm[2];
    float R10=Rm[3],R11=Rm[4],R12=Rm[5];
    float R20=Rm[6],R21=Rm[7],R22=Rm[8];

    float cx = R00*m0 + R01*m1 + R02*m2 + tv[0];
    float cy = R10*m0 + R11*m1 + R12*m2 + tv[1];
    float cz = R20*m0 + R21*m1 + R22*m2 + tv[2];

    float z = cz;
    float depth = fmaxf(z, 1.0f);

    float K00=Km[0],K01=Km[1],K02=Km[2];
    float K10=Km[3],K11=Km[4],K12=Km[5];
    float K20=Km[6],K21=Km[7],K22=Km[8];

    float sx = K00*cx + K01*cy + K02*cz;
    float sy = K10*cx + K11*cy + K12*cz;
    float sz = K20*cx + K21*cy + K22*cz;
    float mx = sx / sz;
    float my = sy / sz;

    // C_cam = R C R^T ; need (0,0), (0,1), (1,1) only
    const float* C = covs3d + 9*i;
    float u0 = R00*C[0] + R01*C[3] + R02*C[6];
    float u1 = R00*C[1] + R01*C[4] + R02*C[7];
    float u2 = R00*C[2] + R01*C[5] + R02*C[8];
    float v0 = R10*C[0] + R11*C[3] + R12*C[6];
    float v1 = R10*C[1] + R11*C[4] + R12*C[7];
    float v2 = R10*C[2] + R11*C[5] + R12*C[8];
    float Cc00 = u0*R00 + u1*R01 + u2*R02;
    float Cc01 = u0*R10 + u1*R11 + u2*R12;
    float Cc11 = v0*R10 + v1*R11 + v2*R12;

    // cov2D: only J[0,0]=fx/z, J[1,1]=fy/z survive the [:2,:2] slice
    float fx = K00, fy = K11;
    float jx = fx / z;
    float jy = fy / z;
    float a = jx*jx*Cc00 + EPSV;
    float b = jx*jy*Cc01;
    float d = jy*jy*Cc11 + EPSV;

    float det    = a*d - b*b;
    float invdet = 1.0f / det;
    float ia =  d * invdet;
    float ib = -b * invdet;
    float id =  a * invdet;

    float norm  = 1.0f / (6.283185307179586f * sqrtf(det));
    bool  valid = (depth > 1.0f) && (depth < 50.0f);
    float coeff = valid ? (opac[i] * norm) : 0.0f;

    // stable depth rank (matches stable jnp.argsort)
    sdepth[i] = depth;
    __syncthreads();
    int r = 0;
    #pragma unroll 8
    for (int j = 0; j < NG; j++) {
        float dj = sdepth[j];
        r += (dj < depth) || ((dj == depth) && (j < i));
    }

    float c0 = colors[3*i+0], c1 = colors[3*i+1], c2 = colors[3*i+2];
    g_params[3*r + 0] = make_float4(mx, my, ia, ib);
    g_params[3*r + 1] = make_float4(id, coeff, c0, c1);
    g_params[3*r + 2] = make_float4(c2, 0.0f, 0.0f, 0.0f);
}

// Render: block = 32x8 pixel tile, 256 threads; warp = one 32-px row
__global__ void __launch_bounds__(256) render_kernel(float* __restrict__ out) {
    __shared__ float4 sg[NG * 3];
    int tid = threadIdx.x;
    #pragma unroll
    for (int k = tid; k < NG * 3; k += 256)
        sg[k] = g_params[k];
    __syncthreads();

    int x = blockIdx.x * 32 + (tid & 31);
    int y = blockIdx.y * 8  + (tid >> 5);
    float px = (float)x;
    float py = (float)y;

    float T = 1.0f;
    float accR = 0.0f, accG = 0.0f, accB = 0.0f;

    #pragma unroll 2
    for (int i = 0; i < NG; i++) {
        float4 p0 = sg[3*i + 0];
        float4 p1 = sg[3*i + 1];
        float dx = px - p0.x;
        float dy = py - p0.y;
        // dxi . dx with symmetric inverse covariance
        float t0 = p0.z * dx + p0.w * dy;
        float t1 = p0.w * dx + p1.x * dy;
        float m  = t0 * dx + t1 * dy;
        if (m < 60.0f) {
            float cb = sg[3*i + 2].x;
            float gs = p1.y * __expf(-0.5f * m);
            float w  = gs * T;
            accR = fmaf(w, p1.z, accR);
            accG = fmaf(w, p1.w, accG);
            accB = fmaf(w, cb,   accB);
            T = T - gs * T;   // T *= (1 - alpha)
        }
    }

    int o = (y * IMG_W + x) * 3;
    out[o + 0] = accR;
    out[o + 1] = accG;
    out[o + 2] = accB;
}

extern "C" void kernel_launch(void* const* d_in, const int* in_sizes, int n_in,
                              void* d_out, int out_size) {
    const float* means3D   = (const float*)d_in[0];
    const float* covs3d    = (const float*)d_in[1];
    const float* colors    = (const float*)d_in[2];
    const float* opacities = (const float*)d_in[3];
    const float* K         = (const float*)d_in[4];
    const float* R         = (const float*)d_in[5];
    const float* t         = (const float*)d_in[6];
    float* out = (float*)d_out;

    project_sort_kernel<<<1, NG>>>(means3D, covs3d, colors, opacities, K, R, t);

    dim3 grid(IMG_W / 32, IMG_H / 8);
    render_kernel<<<grid, 256>>>(out);
}

// round 5
// speedup vs baseline: 1.8668x; 1.8668x over previous
#include <cuda_runtime.h>
#include <math.h>

#define NG 512
#define IMG_H 256
#define IMG_W 256
#define EPSV 1e-4f
#define CUT 60.0f

// Global scratch (sorted by depth rank):
//  g_cull[r] = (mx, my, rx, ry)      conservative ellipse AABB half-extents
//  g_p0[r]   = (mx, my, ia, ib)      mean + inverse-cov upper triangle
//  g_p1[r]   = (id, coeff, colR, colG)
//  g_cb[r]   = colB
__device__ float4 g_cull[NG];
__device__ float4 g_p0[NG];
__device__ float4 g_p1[NG];
__device__ float  g_cb[NG];

// ---------------------------------------------------------------------------
// Projection + stable depth sort. 4 blocks x 128 threads.
// Each block computes all 512 depth keys (redundantly, cheap), then each
// thread fully projects ONE gaussian and computes its stable-sort rank via a
// vectorized O(N) scan of uint64 keys ((depth_bits<<32)|idx == stable argsort).
// ---------------------------------------------------------------------------
__global__ void __launch_bounds__(128) project_kernel(
        const float* __restrict__ means3D,
        const float* __restrict__ covs3d,
        const float* __restrict__ colors,
        const float* __restrict__ opac,
        const float* __restrict__ Km,
        const float* __restrict__ Rm,
        const float* __restrict__ tv) {
    __shared__ __align__(16) unsigned long long skey[NG];
    int tid = threadIdx.x;

    float R00=Rm[0],R01=Rm[1],R02=Rm[2];
    float R10=Rm[3],R11=Rm[4],R12=Rm[5];
    float R20=Rm[6],R21=Rm[7],R22=Rm[8];
    float tx0=tv[0], tx1=tv[1], tx2=tv[2];

    // phase A: all 512 depth keys (depth >= 1 > 0, so float bit order == value order)
    #pragma unroll
    for (int k = 0; k < 4; k++) {
        int g = k * 128 + tid;
        float m0 = means3D[3*g], m1 = means3D[3*g+1], m2 = means3D[3*g+2];
        float cz = R20*m0 + R21*m1 + R22*m2 + tx2;
        float depth = fmaxf(cz, 1.0f);
        skey[g] = ((unsigned long long)__float_as_uint(depth) << 32) | (unsigned)g;
    }
    __syncthreads();

    // phase B: full projection of gaussian i
    int i = blockIdx.x * 128 + tid;
    float m0 = means3D[3*i], m1 = means3D[3*i+1], m2 = means3D[3*i+2];
    float cx = R00*m0 + R01*m1 + R02*m2 + tx0;
    float cy = R10*m0 + R11*m1 + R12*m2 + tx1;
    float cz = R20*m0 + R21*m1 + R22*m2 + tx2;
    float z = cz;
    float depth = fmaxf(z, 1.0f);

    float K00=Km[0],K01=Km[1],K02=Km[2];
    float K10=Km[3],K11=Km[4],K12=Km[5];
    float K20=Km[6],K21=Km[7],K22=Km[8];

    float sx = K00*cx + K01*cy + K02*cz;
    float sy = K10*cx + K11*cy + K12*cz;
    float sz = K20*cx + K21*cy + K22*cz;
    float mx = sx / sz;
    float my = sy / sz;

    // C_cam = R C R^T ; need (0,0), (0,1), (1,1)
    const float* C = covs3d + 9*i;
    float u0 = R00*C[0] + R01*C[3] + R02*C[6];
    float u1 = R00*C[1] + R01*C[4] + R02*C[7];
    float u2 = R00*C[2] + R01*C[5] + R02*C[8];
    float v0 = R10*C[0] + R11*C[3] + R12*C[6];
    float v1 = R10*C[1] + R11*C[4] + R12*C[7];
    float v2 = R10*C[2] + R11*C[5] + R12*C[8];
    float Cc00 = u0*R00 + u1*R01 + u2*R02;
    float Cc01 = u0*R10 + u1*R11 + u2*R12;
    float Cc11 = v0*R10 + v1*R11 + v2*R12;

    // only J[0,0]=fx/z, J[1,1]=fy/z survive the [:2,:2] slice of J^T C J
    float jx = K00 / z;
    float jy = K11 / z;
    float a = jx*jx*Cc00 + EPSV;
    float b = jx*jy*Cc01;
    float d = jy*jy*Cc11 + EPSV;

    float det    = a*d - b*b;
    float invdet = 1.0f / det;
    float ia =  d * invdet;
    float ib = -b * invdet;
    float id =  a * invdet;

    float norm  = 1.0f / (6.283185307179586f * sqrtf(det));
    bool  valid = (depth > 1.0f) && (depth < 50.0f);
    float coeff = valid ? (opac[i] * norm) : 0.0f;

    // exact AABB of the {mahal < CUT} ellipse: half-extent = sqrt(CUT * cov_xx)
    float rxv = valid ? sqrtf(CUT * a) : -1e30f;
    float ryv = valid ? sqrtf(CUT * d) : -1e30f;

    // stable rank: count keys strictly smaller (keys are unique)
    unsigned long long ki = skey[i];
    int r = 0;
    const uint4* sk4 = (const uint4*)skey;
    #pragma unroll 8
    for (int j = 0; j < NG/2; j++) {
        uint4 v = sk4[j];
        unsigned long long k0 = ((unsigned long long)v.y << 32) | v.x;
        unsigned long long k1 = ((unsigned long long)v.w << 32) | v.z;
        r += (int)(k0 < ki) + (int)(k1 < ki);
    }

    float c0 = colors[3*i], c1 = colors[3*i+1], c2 = colors[3*i+2];
    g_cull[r] = make_float4(mx, my, rxv, ryv);
    g_p0[r]   = make_float4(mx, my, ia, ib);
    g_p1[r]   = make_float4(id, coeff, c0, c1);
    g_cb[r]   = c2;
}

// ---------------------------------------------------------------------------
// Render: 32x4 pixel tiles, 128 threads (warp = one 32-px row), 512 blocks.
// Phase 1: cull 512 gaussians against tile AABB, order-preserving compaction
//          into shared memory (ballot + popc + 16-segment scan).
// Phase 2: front-to-back composite over the compact list only.
// ---------------------------------------------------------------------------
__global__ void __launch_bounds__(128) render_kernel(float* __restrict__ out) {
    __shared__ float4 sG1[NG];
    __shared__ float4 sG2[NG];
    __shared__ float  sCB[NG];
    __shared__ int segTot[16];
    __shared__ int segOff[16];
    __shared__ int sCount;

    int tid  = threadIdx.x;
    int lane = tid & 31;
    int wrp  = tid >> 5;

    float x0 = (float)(blockIdx.x * 32);
    float y0 = (float)(blockIdx.y * 4);
    float x1 = x0 + 31.0f;
    float y1 = y0 + 3.0f;

    // pass 1: flags + per-(chunk,warp) segment totals (order: chunk-major)
    unsigned flags = 0;
    #pragma unroll
    for (int k = 0; k < 4; k++) {
        int g = k * 128 + tid;
        float4 c = g_cull[g];
        bool keep = (c.x + c.z >= x0) && (c.x - c.z <= x1) &&
                    (c.y + c.w >= y0) && (c.y - c.w <= y1);
        unsigned mask = __ballot_sync(0xffffffffu, keep);
        if (lane == 0) segTot[k * 4 + wrp] = __popc(mask);
        flags |= keep ? (1u << k) : 0u;
    }
    __syncthreads();

    // exclusive scan over the 16 segment totals (warp 0, lanes 0..15)
    if (tid < 16) {
        int v = segTot[tid];
        int x = v;
        #pragma unroll
        for (int dd = 1; dd < 16; dd <<= 1) {
            int n = __shfl_up_sync(0x0000ffffu, x, dd);
            if (tid >= dd) x += n;
        }
        segOff[tid] = x - v;
        if (tid == 15) sCount = x;
    }
    __syncthreads();

    // pass 2: order-preserving scatter of surviving gaussians into smem
    #pragma unroll
    for (int k = 0; k < 4; k++) {
        bool keep = (flags >> k) & 1u;
        unsigned mask = __ballot_sync(0xffffffffu, keep);
        if (keep) {
            int pos = segOff[k * 4 + wrp] + __popc(mask & ((1u << lane) - 1u));
            int g = k * 128 + tid;
            sG1[pos] = g_p0[g];
            sG2[pos] = g_p1[g];
            sCB[pos] = g_cb[g];
        }
    }
    __syncthreads();
    int count = sCount;

    float px = x0 + (float)lane;
    float py = y0 + (float)wrp;
    float T = 1.0f;
    float accR = 0.0f, accG = 0.0f, accB = 0.0f;

    #pragma unroll 2
    for (int i = 0; i < count; i++) {
        float4 p0 = sG1[i];
        float4 p1 = sG2[i];
        float dx = px - p0.x;
        float dy = py - p0.y;
        float tx = fmaf(p0.z, dx, p0.w * dy);   // ia*dx + ib*dy
        float ty = fmaf(p0.w, dx, p1.x * dy);   // ib*dx + id*dy
        float m  = fmaf(tx, dx, ty * dy);
        if (m < CUT) {
            float gs  = p1.y * __expf(-0.5f * m);  // alpha
            float wgt = gs * T;
            accR = fmaf(wgt, p1.z, accR);
            accG = fmaf(wgt, p1.w, accG);
            accB = fmaf(wgt, sCB[i], accB);
            T -= wgt;                               // T *= (1 - alpha)
        }
    }

    int x = blockIdx.x * 32 + lane;
    int y = blockIdx.y * 4 + wrp;
    int o = (y * IMG_W + x) * 3;
    out[o + 0] = accR;
    out[o + 1] = accG;
    out[o + 2] = accB;
}

extern "C" void kernel_launch(void* const* d_in, const int* in_sizes, int n_in,
                              void* d_out, int out_size) {
    const float* means3D   = (const float*)d_in[0];
    const float* covs3d    = (const float*)d_in[1];
    const float* colors    = (const float*)d_in[2];
    const float* opacities = (const float*)d_in[3];
    const float* K         = (const float*)d_in[4];
    const float* R         = (const float*)d_in[5];
    const float* t         = (const float*)d_in[6];
    float* out = (float*)d_out;

    project_kernel<<<4, 128>>>(means3D, covs3d, colors, opacities, K, R, t);

    dim3 grid(IMG_W / 32, IMG_H / 4);
    render_kernel<<<grid, 128>>>(out);
}

// round 6
// speedup vs baseline: 1.8875x; 1.0111x over previous
#include <cuda_runtime.h>
#include <math.h>

#define NG 512
#define IMG_H 256
#define IMG_W 256
#define EPSV 1e-4f
#define CUT 50.0f

// Global scratch (sorted by depth rank):
//  g_cull[r] = (mx, my, rx, ry)      conservative ellipse AABB half-extents
//  g_p0[r]   = (mx, my, ia, ib)      mean + inverse-cov entries
//  g_p1[r]   = (id, coeff, colR, colG)
//  g_cb[r]   = colB
__device__ float4 g_cull[NG];
__device__ float4 g_p0[NG];
__device__ float4 g_p1[NG];
__device__ float  g_cb[NG];

// ---------------------------------------------------------------------------
// Projection + stable depth sort. 4 blocks x 128 threads.
// uint64 key (depth_bits<<32 | idx) rank == stable jnp.argsort.
// ---------------------------------------------------------------------------
__global__ void __launch_bounds__(128) project_kernel(
        const float* __restrict__ means3D,
        const float* __restrict__ covs3d,
        const float* __restrict__ colors,
        const float* __restrict__ opac,
        const float* __restrict__ Km,
        const float* __restrict__ Rm,
        const float* __restrict__ tv) {
    __shared__ __align__(16) unsigned long long skey[NG];
    int tid = threadIdx.x;

    float R00=Rm[0],R01=Rm[1],R02=Rm[2];
    float R10=Rm[3],R11=Rm[4],R12=Rm[5];
    float R20=Rm[6],R21=Rm[7],R22=Rm[8];
    float tx0=tv[0], tx1=tv[1], tx2=tv[2];

    // phase A: all 512 depth keys (depth >= 1 > 0 so float bit order == order)
    #pragma unroll
    for (int k = 0; k < 4; k++) {
        int g = k * 128 + tid;
        float m0 = means3D[3*g], m1 = means3D[3*g+1], m2 = means3D[3*g+2];
        float cz = R20*m0 + R21*m1 + R22*m2 + tx2;
        float depth = fmaxf(cz, 1.0f);
        skey[g] = ((unsigned long long)__float_as_uint(depth) << 32) | (unsigned)g;
    }
    __syncthreads();

    // phase B: full projection of gaussian i
    int i = blockIdx.x * 128 + tid;
    float m0 = means3D[3*i], m1 = means3D[3*i+1], m2 = means3D[3*i+2];
    float cx = R00*m0 + R01*m1 + R02*m2 + tx0;
    float cy = R10*m0 + R11*m1 + R12*m2 + tx1;
    float cz = R20*m0 + R21*m1 + R22*m2 + tx2;
    float z = cz;
    float depth = fmaxf(z, 1.0f);

    float K00=Km[0],K01=Km[1],K02=Km[2];
    float K10=Km[3],K11=Km[4],K12=Km[5];
    float K20=Km[6],K21=Km[7],K22=Km[8];

    float sx = K00*cx + K01*cy + K02*cz;
    float sy = K10*cx + K11*cy + K12*cz;
    float sz = K20*cx + K21*cy + K22*cz;
    float mx = sx / sz;
    float my = sy / sz;

    // C_cam = R C R^T ; need (0,0), (0,1), (1,1)
    const float* C = covs3d + 9*i;
    float u0 = R00*C[0] + R01*C[3] + R02*C[6];
    float u1 = R00*C[1] + R01*C[4] + R02*C[7];
    float u2 = R00*C[2] + R01*C[5] + R02*C[8];
    float v0 = R10*C[0] + R11*C[3] + R12*C[6];
    float v1 = R10*C[1] + R11*C[4] + R12*C[7];
    float v2 = R10*C[2] + R11*C[5] + R12*C[8];
    float Cc00 = u0*R00 + u1*R01 + u2*R02;
    float Cc01 = u0*R10 + u1*R11 + u2*R12;
    float Cc11 = v0*R10 + v1*R11 + v2*R12;

    // only J[0,0]=fx/z, J[1,1]=fy/z survive the [:2,:2] slice of J^T C J
    float jx = K00 / z;
    float jy = K11 / z;
    float a = jx*jx*Cc00 + EPSV;
    float b = jx*jy*Cc01;
    float d = jy*jy*Cc11 + EPSV;

    float det    = a*d - b*b;
    float invdet = 1.0f / det;
    float ia =  d * invdet;
    float ib = -b * invdet;
    float id =  a * invdet;

    float norm  = 1.0f / (6.283185307179586f * sqrtf(det));
    bool  valid = (depth > 1.0f) && (depth < 50.0f);
    float coeff = valid ? (opac[i] * norm) : 0.0f;

    // exact AABB of the {mahal < CUT} ellipse
    float rxv = valid ? sqrtf(CUT * a) : -1e30f;
    float ryv = valid ? sqrtf(CUT * d) : -1e30f;

    // stable rank: count keys strictly smaller (keys are unique)
    unsigned long long ki = skey[i];
    int r = 0;
    const uint4* sk4 = (const uint4*)skey;
    #pragma unroll 8
    for (int j = 0; j < NG/2; j++) {
        uint4 v = sk4[j];
        unsigned long long k0 = ((unsigned long long)v.y << 32) | v.x;
        unsigned long long k1 = ((unsigned long long)v.w << 32) | v.z;
        r += (int)(k0 < ki) + (int)(k1 < ki);
    }

    float c0 = colors[3*i], c1 = colors[3*i+1], c2 = colors[3*i+2];
    g_cull[r] = make_float4(mx, my, rxv, ryv);
    g_p0[r]   = make_float4(mx, my, ia, ib);
    g_p1[r]   = make_float4(id, coeff, c0, c1);
    g_cb[r]   = c2;
}

// ---------------------------------------------------------------------------
// Render: 32x8 pixel tiles, 128 threads, 2 pixels/thread (rows w and w+4).
// Phase 1: order-preserving compaction of gaussians passing the tile AABB.
// Phase 2: software-pipelined front-to-back compositing, 2 px per thread.
// ---------------------------------------------------------------------------
__global__ void __launch_bounds__(128) render_kernel(float* __restrict__ out) {
    __shared__ float4 sG1[NG];
    __shared__ float4 sG2[NG];
    __shared__ float  sCB[NG];
    __shared__ int segTot[16];
    __shared__ int segOff[16];
    __shared__ int sCount;

    int tid  = threadIdx.x;
    int lane = tid & 31;
    int wrp  = tid >> 5;

    float x0 = (float)(blockIdx.x * 32);
    float y0 = (float)(blockIdx.y * 8);
    float x1 = x0 + 31.0f;
    float y1 = y0 + 7.0f;

    // pass 1: flags + per-(chunk,warp) segment totals (chunk-major order)
    unsigned flags = 0;
    #pragma unroll
    for (int k = 0; k < 4; k++) {
        int g = k * 128 + tid;
        float4 c = g_cull[g];
        bool keep = (c.x + c.z >= x0) && (c.x - c.z <= x1) &&
                    (c.y + c.w >= y0) && (c.y - c.w <= y1);
        unsigned mask = __ballot_sync(0xffffffffu, keep);
        if (lane == 0) segTot[k * 4 + wrp] = __popc(mask);
        flags |= keep ? (1u << k) : 0u;
    }
    __syncthreads();

    // exclusive scan over the 16 segment totals
    if (tid < 16) {
        int v = segTot[tid];
        int x = v;
        #pragma unroll
        for (int dd = 1; dd < 16; dd <<= 1) {
            int n = __shfl_up_sync(0x0000ffffu, x, dd);
            if (tid >= dd) x += n;
        }
        segOff[tid] = x - v;
        if (tid == 15) sCount = x;
    }
    __syncthreads();

    // pass 2: order-preserving scatter into smem
    #pragma unroll
    for (int k = 0; k < 4; k++) {
        bool keep = (flags >> k) & 1u;
        unsigned mask = __ballot_sync(0xffffffffu, keep);
        if (keep) {
            int pos = segOff[k * 4 + wrp] + __popc(mask & ((1u << lane) - 1u));
            int g = k * 128 + tid;
            sG1[pos] = g_p0[g];
            sG2[pos] = g_p1[g];
            sCB[pos] = g_cb[g];
        }
    }
    __syncthreads();
    int count = sCount;

    float px  = x0 + (float)lane;
    float py0 = y0 + (float)wrp;          // row w
    float py1 = py0 + 4.0f;               // row w+4

    float T0 = 1.0f, T1 = 1.0f;
    float aR0 = 0.f, aG0 = 0.f, aB0 = 0.f;
    float aR1 = 0.f, aG1 = 0.f, aB1 = 0.f;

    // software-pipelined loop: prefetch i+1 while compositing i
    float4 p0, p1;
    float  cb;
    if (count > 0) { p0 = sG1[0]; p1 = sG2[0]; cb = sCB[0]; }

    for (int i = 0; i < count; i++) {
        float4 n0, n1;
        float  ncb;
        int j = i + 1;
        if (j < count) { n0 = sG1[j]; n1 = sG2[j]; ncb = sCB[j]; }

        float dx  = px  - p0.x;
        float dy0 = py0 - p0.y;
        float dy1 = py1 - p0.y;
        // m = ia*dx^2 + 2*ib*dx*dy + id*dy^2
        float tx  = fmaf(p0.z, dx, p0.w * dy0);
        float ty  = fmaf(p0.w, dx, p1.x * dy0);
        float m0  = fmaf(tx, dx, ty * dy0);
        float ux  = fmaf(p0.z, dx, p0.w * dy1);
        float uy  = fmaf(p0.w, dx, p1.x * dy1);
        float m1  = fmaf(ux, dx, uy * dy1);

        if (fminf(m0, m1) < CUT) {
            float e0 = p1.y * __expf(-0.5f * m0);
            float e1 = p1.y * __expf(-0.5f * m1);
            float w0 = e0 * T0;
            float w1 = e1 * T1;
            aR0 = fmaf(w0, p1.z, aR0);
            aG0 = fmaf(w0, p1.w, aG0);
            aB0 = fmaf(w0, cb,   aB0);
            aR1 = fmaf(w1, p1.z, aR1);
            aG1 = fmaf(w1, p1.w, aG1);
            aB1 = fmaf(w1, cb,   aB1);
            T0 -= w0;
            T1 -= w1;
        }

        p0 = n0; p1 = n1; cb = ncb;
    }

    int x  = blockIdx.x * 32 + lane;
    int yA = blockIdx.y * 8 + wrp;
    int yB = yA + 4;
    int oA = (yA * IMG_W + x) * 3;
    int oB = (yB * IMG_W + x) * 3;
    out[oA + 0] = aR0;
    out[oA + 1] = aG0;
    out[oA + 2] = aB0;
    out[oB + 0] = aR1;
    out[oB + 1] = aG1;
    out[oB + 2] = aB1;
}

extern "C" void kernel_launch(void* const* d_in, const int* in_sizes, int n_in,
                              void* d_out, int out_size) {
    const float* means3D   = (const float*)d_in[0];
    const float* covs3d    = (const float*)d_in[1];
    const float* colors    = (const float*)d_in[2];
    const float* opacities = (const float*)d_in[3];
    const float* K         = (const float*)d_in[4];
    const float* R         = (const float*)d_in[5];
    const float* t         = (const float*)d_in[6];
    float* out = (float*)d_out;

    project_kernel<<<4, 128>>>(means3D, covs3d, colors, opacities, K, R, t);

    dim3 grid(IMG_W / 32, IMG_H / 8);
    render_kernel<<<grid, 128>>>(out);
}

// round 7
// speedup vs baseline: 2.2956x; 1.2162x over previous
#include <cuda_runtime.h>
#include <math.h>

#define NG 512
#define NSEG 4
#define SEGSZ 128
#define IMG_H 256
#define IMG_W 256
#define NPIX (IMG_H * IMG_W)
#define EPSV 1e-4f
#define CUT 50.0f

// Sorted-by-depth gaussian params:
//  g_cull[r] = (mx, my, rx, ry)   conservative ellipse AABB half-extents
//  g_p0[r]   = (mx, my, ia, ib)   mean + inverse-cov entries
//  g_p1[r]   = (id, coeff, colR, colG)
//  g_cb[r]   = colB
__device__ float4 g_cull[NG];
__device__ float4 g_p0[NG];
__device__ float4 g_p1[NG];
__device__ float  g_cb[NG];
// Per-segment partial composites: (R, G, B, T) per pixel, segment-major.
__device__ float4 g_seg[NSEG * NPIX];

// ---------------------------------------------------------------------------
// Projection + stable depth sort. 4 blocks x 256 threads.
// Threads [0,128): project gaussian i and scan keys [0,256) for its rank.
// Threads [128,256): scan keys [256,512) for the same gaussian (split rank).
// uint64 key (depth_bits<<32 | idx) rank == stable jnp.argsort.
// ---------------------------------------------------------------------------
__global__ void __launch_bounds__(256) project_kernel(
        const float* __restrict__ means3D,
        const float* __restrict__ covs3d,
        const float* __restrict__ colors,
        const float* __restrict__ opac,
        const float* __restrict__ Km,
        const float* __restrict__ Rm,
        const float* __restrict__ tv) {
    __shared__ __align__(16) unsigned long long skey[NG];
    __shared__ int partial[128];
    int tid = threadIdx.x;

    float R20=Rm[6],R21=Rm[7],R22=Rm[8];
    float tx2=tv[2];

    // phase A: all 512 depth keys (depth >= 1 > 0 so float bit order == order)
    #pragma unroll
    for (int k = 0; k < 2; k++) {
        int g = k * 256 + tid;
        float m0 = means3D[3*g], m1 = means3D[3*g+1], m2 = means3D[3*g+2];
        float cz = R20*m0 + R21*m1 + R22*m2 + tx2;
        float depth = fmaxf(cz, 1.0f);
        skey[g] = ((unsigned long long)__float_as_uint(depth) << 32) | (unsigned)g;
    }
    __syncthreads();

    int half = tid >> 7;        // 0 or 1
    int li   = tid & 127;
    int i    = blockIdx.x * 128 + li;

    // split stable rank: each half counts smaller keys in its 256-key range
    unsigned long long ki = skey[i];
    int r = 0;
    const uint4* sk4 = (const uint4*)skey;
    int jbase = half * 128;     // uint4 index: 128 uint4 = 256 keys
    #pragma unroll 8
    for (int j = 0; j < 128; j++) {
        uint4 v = sk4[jbase + j];
        unsigned long long k0 = ((unsigned long long)v.y << 32) | v.x;
        unsigned long long k1 = ((unsigned long long)v.w << 32) | v.z;
        r += (int)(k0 < ki) + (int)(k1 < ki);
    }
    if (half == 1) partial[li] = r;
    __syncthreads();
    if (half == 1) return;
    r += partial[li];

    // full projection of gaussian i
    float R00=Rm[0],R01=Rm[1],R02=Rm[2];
    float R10=Rm[3],R11=Rm[4],R12=Rm[5];
    float tx0=tv[0], tx1=tv[1];

    float m0 = means3D[3*i], m1 = means3D[3*i+1], m2 = means3D[3*i+2];
    float cx = R00*m0 + R01*m1 + R02*m2 + tx0;
    float cy = R10*m0 + R11*m1 + R12*m2 + tx1;
    float cz = R20*m0 + R21*m1 + R22*m2 + tx2;
    float z = cz;
    float depth = fmaxf(z, 1.0f);

    float K00=Km[0],K01=Km[1],K02=Km[2];
    float K10=Km[3],K11=Km[4],K12=Km[5];
    float K20=Km[6],K21=Km[7],K22=Km[8];

    float sx = K00*cx + K01*cy + K02*cz;
    float sy = K10*cx + K11*cy + K12*cz;
    float sz = K20*cx + K21*cy + K22*cz;
    float mx = sx / sz;
    float my = sy / sz;

    // C_cam = R C R^T ; need (0,0), (0,1), (1,1)
    const float* C = covs3d + 9*i;
    float u0 = R00*C[0] + R01*C[3] + R02*C[6];
    float u1 = R00*C[1] + R01*C[4] + R02*C[7];
    float u2 = R00*C[2] + R01*C[5] + R02*C[8];
    float v0 = R10*C[0] + R11*C[3] + R12*C[6];
    float v1 = R10*C[1] + R11*C[4] + R12*C[7];
    float v2 = R10*C[2] + R11*C[5] + R12*C[8];
    float Cc00 = u0*R00 + u1*R01 + u2*R02;
    float Cc01 = u0*R10 + u1*R11 + u2*R12;
    float Cc11 = v0*R10 + v1*R11 + v2*R12;

    // only J[0,0]=fx/z, J[1,1]=fy/z survive the [:2,:2] slice of J^T C J
    float jx = K00 / z;
    float jy = K11 / z;
    float a = jx*jx*Cc00 + EPSV;
    float b = jx*jy*Cc01;
    float d = jy*jy*Cc11 + EPSV;

    float det    = a*d - b*b;
    float invdet = 1.0f / det;
    float ia =  d * invdet;
    float ib = -b * invdet;
    float id =  a * invdet;

    float norm  = 1.0f / (6.283185307179586f * sqrtf(det));
    bool  valid = (depth > 1.0f) && (depth < 50.0f);
    float coeff = valid ? (opac[i] * norm) : 0.0f;

    // exact AABB of the {mahal < CUT} ellipse
    float rxv = valid ? sqrtf(CUT * a) : -1e30f;
    float ryv = valid ? sqrtf(CUT * d) : -1e30f;

    float c0 = colors[3*i], c1 = colors[3*i+1], c2 = colors[3*i+2];
    g_cull[r] = make_float4(mx, my, rxv, ryv);
    g_p0[r]   = make_float4(mx, my, ia, ib);
    g_p1[r]   = make_float4(id, coeff, c0, c1);
    g_cb[r]   = c2;
}

// ---------------------------------------------------------------------------
// Render partials: grid (8, 32, 4) = (tile_x, tile_y, depth segment).
// 32x8 pixel tile, 128 threads, 2 pixels/thread (rows w and w+4).
// Each block culls its 128-gaussian depth segment against the tile AABB
// (order-preserving compaction), composites front-to-back within the
// segment, and writes per-pixel (R,G,B,T) partials to g_seg.
// ---------------------------------------------------------------------------
__global__ void __launch_bounds__(128) render_kernel() {
    __shared__ float4 sG1[SEGSZ];
    __shared__ float4 sG2[SEGSZ];
    __shared__ float  sCB[SEGSZ];
    __shared__ int segTot[4];
    __shared__ int segOff[4];
    __shared__ int sCount;

    int tid  = threadIdx.x;
    int lane = tid & 31;
    int wrp  = tid >> 5;
    int seg  = blockIdx.z;

    float x0 = (float)(blockIdx.x * 32);
    float y0 = (float)(blockIdx.y * 8);
    float x1 = x0 + 31.0f;
    float y1 = y0 + 7.0f;

    // cull this segment's 128 gaussians against the tile AABB
    int g = seg * SEGSZ + tid;
    float4 c = g_cull[g];
    bool keep = (c.x + c.z >= x0) && (c.x - c.z <= x1) &&
                (c.y + c.w >= y0) && (c.y - c.w <= y1);
    unsigned mask = __ballot_sync(0xffffffffu, keep);
    if (lane == 0) segTot[wrp] = __popc(mask);
    __syncthreads();
    if (tid == 0) {
        int s = 0;
        #pragma unroll
        for (int w = 0; w < 4; w++) { segOff[w] = s; s += segTot[w]; }
        sCount = s;
    }
    __syncthreads();

    // order-preserving scatter into smem
    if (keep) {
        int pos = segOff[wrp] + __popc(mask & ((1u << lane) - 1u));
        sG1[pos] = g_p0[g];
        sG2[pos] = g_p1[g];
        sCB[pos] = g_cb[g];
    }
    __syncthreads();
    int count = sCount;

    int x  = blockIdx.x * 32 + lane;
    int yA = blockIdx.y * 8 + wrp;
    int yB = yA + 4;
    int oA = seg * NPIX + yA * IMG_W + x;
    int oB = seg * NPIX + yB * IMG_W + x;

    if (count == 0) {
        g_seg[oA] = make_float4(0.f, 0.f, 0.f, 1.f);
        g_seg[oB] = make_float4(0.f, 0.f, 0.f, 1.f);
        return;
    }

    float px  = x0 + (float)lane;
    float py0 = y0 + (float)wrp;
    float py1 = py0 + 4.0f;

    float T0 = 1.0f, T1 = 1.0f;
    float aR0 = 0.f, aG0 = 0.f, aB0 = 0.f;
    float aR1 = 0.f, aG1 = 0.f, aB1 = 0.f;

    // software-pipelined loop: prefetch i+1 while compositing i
    float4 p0 = sG1[0], p1 = sG2[0];
    float  cb = sCB[0];

    for (int i = 0; i < count; i++) {
        float4 n0, n1;
        float  ncb;
        int j = i + 1;
        if (j < count) { n0 = sG1[j]; n1 = sG2[j]; ncb = sCB[j]; }

        float dx  = px  - p0.x;
        float dy0 = py0 - p0.y;
        float dy1 = py1 - p0.y;
        float tx  = fmaf(p0.z, dx, p0.w * dy0);
        float ty  = fmaf(p0.w, dx, p1.x * dy0);
        float m0  = fmaf(tx, dx, ty * dy0);
        float ux  = fmaf(p0.z, dx, p0.w * dy1);
        float uy  = fmaf(p0.w, dx, p1.x * dy1);
        float m1  = fmaf(ux, dx, uy * dy1);

        if (fminf(m0, m1) < CUT) {
            float e0 = p1.y * __expf(-0.5f * m0);
            float e1 = p1.y * __expf(-0.5f * m1);
            float w0 = e0 * T0;
            float w1 = e1 * T1;
            aR0 = fmaf(w0, p1.z, aR0);
            aG0 = fmaf(w0, p1.w, aG0);
            aB0 = fmaf(w0, cb,   aB0);
            aR1 = fmaf(w1, p1.z, aR1);
            aG1 = fmaf(w1, p1.w, aG1);
            aB1 = fmaf(w1, cb,   aB1);
            T0 -= w0;
            T1 -= w1;
        }

        p0 = n0; p1 = n1; cb = ncb;
    }

    g_seg[oA] = make_float4(aR0, aG0, aB0, T0);
    g_seg[oB] = make_float4(aR1, aG1, aB1, T1);
}

// ---------------------------------------------------------------------------
// Merge: out = c0 + T0*(c1 + T1*(c2 + T2*c3)) per pixel.
// ---------------------------------------------------------------------------
__global__ void __launch_bounds__(256) merge_kernel(float* __restrict__ out) {
    int pix = blockIdx.x * 256 + threadIdx.x;
    float4 s0 = g_seg[pix];
    float4 s1 = g_seg[pix + NPIX];
    float4 s2 = g_seg[pix + 2 * NPIX];
    float4 s3 = g_seg[pix + 3 * NPIX];

    float R = fmaf(s2.w, s3.x, s2.x);
    float G = fmaf(s2.w, s3.y, s2.y);
    float B = fmaf(s2.w, s3.z, s2.z);
    R = fmaf(s1.w, R, s1.x);
    G = fmaf(s1.w, G, s1.y);
    B = fmaf(s1.w, B, s1.z);
    R = fmaf(s0.w, R, s0.x);
    G = fmaf(s0.w, G, s0.y);
    B = fmaf(s0.w, B, s0.z);

    int o = pix * 3;
    out[o + 0] = R;
    out[o + 1] = G;
    out[o + 2] = B;
}

extern "C" void kernel_launch(void* const* d_in, const int* in_sizes, int n_in,
                              void* d_out, int out_size) {
    const float* means3D   = (const float*)d_in[0];
    const float* covs3d    = (const float*)d_in[1];
    const float* colors    = (const float*)d_in[2];
    const float* opacities = (const float*)d_in[3];
    const float* K         = (const float*)d_in[4];
    const float* R         = (const float*)d_in[5];
    const float* t         = (const float*)d_in[6];
    float* out = (float*)d_out;

    project_kernel<<<4, 256>>>(means3D, covs3d, colors, opacities, K, R, t);

    dim3 grid(IMG_W / 32, IMG_H / 8, NSEG);
    render_kernel<<<grid, 128>>>();

    merge_kernel<<<NPIX / 256, 256>>>(out);
}

// round 8
// speedup vs baseline: 2.5985x; 1.1319x over previous
#include <cuda_runtime.h>
#include <math.h>

#define NG 512
#define NSEG 4
#define SEGSZ 128
#define IMG_H 256
#define IMG_W 256
#define NPIX (IMG_H * IMG_W)
#define EPSV 1e-4f
#define CUT 50.0f

// Sorted-by-depth gaussian params:
//  g_cull[r] = (mx, my, rx, ry)   conservative ellipse AABB half-extents
//  g_p0[r]   = (mx, my, ia, ib)   mean + inverse-cov entries
//  g_p1[r]   = (id, coeff, colR, colG)
//  g_cb[r]   = colB
__device__ float4 g_cull[NG];
__device__ float4 g_p0[NG];
__device__ float4 g_p1[NG];
__device__ float  g_cb[NG];
// Per-segment partial composites: (R, G, B, T) per pixel, segment-major.
__device__ float4 g_seg[NSEG * NPIX];

// ---------------------------------------------------------------------------
// Projection + stable depth sort. 32 blocks x 512 threads.
// Each block computes all 512 depth keys (1 key/thread, redundant across
// blocks). Each of the block's 16 warps owns one gaussian:
//   - all 32 lanes redundantly compute the full projection (overlaps the
//     global-load latency with the rank scan below),
//   - the 32 lanes scan 8 uint4 keys each (conflict-free interleave),
//   - redux.add gives the stable rank; lane 0 stores.
// uint64 key (depth_bits<<32 | idx) rank == stable jnp.argsort.
// ---------------------------------------------------------------------------
__global__ void __launch_bounds__(512) project_kernel(
        const float* __restrict__ means3D,
        const float* __restrict__ covs3d,
        const float* __restrict__ colors,
        const float* __restrict__ opac,
        const float* __restrict__ Km,
        const float* __restrict__ Rm,
        const float* __restrict__ tv) {
    __shared__ __align__(16) unsigned long long skey[NG];
    int tid  = threadIdx.x;
    int warp = tid >> 5;
    int lane = tid & 31;

    float R00=Rm[0],R01=Rm[1],R02=Rm[2];
    float R10=Rm[3],R11=Rm[4],R12=Rm[5];
    float R20=Rm[6],R21=Rm[7],R22=Rm[8];
    float tx0=tv[0], tx1=tv[1], tx2=tv[2];

    // phase A: key for gaussian 'tid' (depth >= 1 > 0: float bit order == order)
    {
        float m0 = means3D[3*tid], m1 = means3D[3*tid+1], m2 = means3D[3*tid+2];
        float cz = R20*m0 + R21*m1 + R22*m2 + tx2;
        float depth = fmaxf(cz, 1.0f);
        skey[tid] = ((unsigned long long)__float_as_uint(depth) << 32) | (unsigned)tid;
    }

    // phase B: full projection of this warp's gaussian (all lanes, redundant —
    // issues the LDGs early so their latency overlaps the rank scan)
    int i = blockIdx.x * 16 + warp;

    float m0 = means3D[3*i], m1 = means3D[3*i+1], m2 = means3D[3*i+2];
    const float* C = covs3d + 9*i;
    float C0=C[0],C1=C[1],C2=C[2],C3=C[3],C4=C[4],C5=C[5],C6=C[6],C7=C[7],C8=C[8];
    float c0 = colors[3*i], c1 = colors[3*i+1], c2 = colors[3*i+2];
    float op = opac[i];

    float cx = R00*m0 + R01*m1 + R02*m2 + tx0;
    float cy = R10*m0 + R11*m1 + R12*m2 + tx1;
    float cz = R20*m0 + R21*m1 + R22*m2 + tx2;
    float z = cz;
    float depth = fmaxf(z, 1.0f);

    float K00=Km[0],K01=Km[1],K02=Km[2];
    float K10=Km[3],K11=Km[4],K12=Km[5];
    float K20=Km[6],K21=Km[7],K22=Km[8];

    float sx = K00*cx + K01*cy + K02*cz;
    float sy = K10*cx + K11*cy + K12*cz;
    float sz = K20*cx + K21*cy + K22*cz;
    float mx = sx / sz;
    float my = sy / sz;

    // C_cam = R C R^T ; need (0,0), (0,1), (1,1)
    float u0 = R00*C0 + R01*C3 + R02*C6;
    float u1 = R00*C1 + R01*C4 + R02*C7;
    float u2 = R00*C2 + R01*C5 + R02*C8;
    float v0 = R10*C0 + R11*C3 + R12*C6;
    float v1 = R10*C1 + R11*C4 + R12*C7;
    float v2 = R10*C2 + R11*C5 + R12*C8;
    float Cc00 = u0*R00 + u1*R01 + u2*R02;
    float Cc01 = u0*R10 + u1*R11 + u2*R12;
    float Cc11 = v0*R10 + v1*R11 + v2*R12;

    // only J[0,0]=fx/z, J[1,1]=fy/z survive the [:2,:2] slice of J^T C J
    float jx = K00 / z;
    float jy = K11 / z;
    float a = jx*jx*Cc00 + EPSV;
    float b = jx*jy*Cc01;
    float d = jy*jy*Cc11 + EPSV;

    float det    = a*d - b*b;
    float invdet = 1.0f / det;
    float ia =  d * invdet;
    float ib = -b * invdet;
    float id =  a * invdet;

    float norm  = 1.0f / (6.283185307179586f * sqrtf(det));
    bool  valid = (depth > 1.0f) && (depth < 50.0f);
    float coeff = valid ? (op * norm) : 0.0f;

    // exact AABB of the {mahal < CUT} ellipse
    float rxv = valid ? sqrtf(CUT * a) : -1e30f;
    float ryv = valid ? sqrtf(CUT * d) : -1e30f;

    __syncthreads();

    // phase C: warp-cooperative stable rank (count strictly-smaller keys).
    // Interleaved uint4 access: addr stride 16B per lane -> conflict-free.
    unsigned long long ki = skey[i];
    const uint4* sk4 = (const uint4*)skey;   // 256 uint4
    int r = 0;
    #pragma unroll
    for (int j = 0; j < 8; j++) {
        uint4 v = sk4[j * 32 + lane];
        unsigned long long k0 = ((unsigned long long)v.y << 32) | v.x;
        unsigned long long k1 = ((unsigned long long)v.w << 32) | v.z;
        r += (int)(k0 < ki) + (int)(k1 < ki);
    }
    r = __reduce_add_sync(0xffffffffu, r);

    if (lane == 0) {
        g_cull[r] = make_float4(mx, my, rxv, ryv);
        g_p0[r]   = make_float4(mx, my, ia, ib);
        g_p1[r]   = make_float4(id, coeff, c0, c1);
        g_cb[r]   = c2;
    }
}

// ---------------------------------------------------------------------------
// Render partials: grid (8, 32, 4) = (tile_x, tile_y, depth segment).
// 32x8 pixel tile, 128 threads, 2 pixels/thread (rows w and w+4).
// Each block culls its 128-gaussian depth segment against the tile AABB
// (order-preserving compaction), composites front-to-back within the
// segment, and writes per-pixel (R,G,B,T) partials to g_seg.
// ---------------------------------------------------------------------------
__global__ void __launch_bounds__(128) render_kernel() {
    __shared__ float4 sG1[SEGSZ];
    __shared__ float4 sG2[SEGSZ];
    __shared__ float  sCB[SEGSZ];
    __shared__ int segTot[4];
    __shared__ int segOff[4];
    __shared__ int sCount;

    int tid  = threadIdx.x;
    int lane = tid & 31;
    int wrp  = tid >> 5;
    int seg  = blockIdx.z;

    float x0 = (float)(blockIdx.x * 32);
    float y0 = (float)(blockIdx.y * 8);
    float x1 = x0 + 31.0f;
    float y1 = y0 + 7.0f;

    // cull this segment's 128 gaussians against the tile AABB
    int g = seg * SEGSZ + tid;
    float4 c = g_cull[g];
    bool keep = (c.x + c.z >= x0) && (c.x - c.z <= x1) &&
                (c.y + c.w >= y0) && (c.y - c.w <= y1);
    unsigned mask = __ballot_sync(0xffffffffu, keep);
    if (lane == 0) segTot[wrp] = __popc(mask);
    __syncthreads();
    if (tid == 0) {
        int s = 0;
        #pragma unroll
        for (int w = 0; w < 4; w++) { segOff[w] = s; s += segTot[w]; }
        sCount = s;
    }
    __syncthreads();

    // order-preserving scatter into smem
    if (keep) {
        int pos = segOff[wrp] + __popc(mask & ((1u << lane) - 1u));
        sG1[pos] = g_p0[g];
        sG2[pos] = g_p1[g];
        sCB[pos] = g_cb[g];
    }
    __syncthreads();
    int count = sCount;

    int x  = blockIdx.x * 32 + lane;
    int yA = blockIdx.y * 8 + wrp;
    int yB = yA + 4;
    int oA = seg * NPIX + yA * IMG_W + x;
    int oB = seg * NPIX + yB * IMG_W + x;

    if (count == 0) {
        g_seg[oA] = make_float4(0.f, 0.f, 0.f, 1.f);
        g_seg[oB] = make_float4(0.f, 0.f, 0.f, 1.f);
        return;
    }

    float px  = x0 + (float)lane;
    float py0 = y0 + (float)wrp;
    float py1 = py0 + 4.0f;

    float T0 = 1.0f, T1 = 1.0f;
    float aR0 = 0.f, aG0 = 0.f, aB0 = 0.f;
    float aR1 = 0.f, aG1 = 0.f, aB1 = 0.f;

    // software-pipelined loop: prefetch i+1 while compositing i
    float4 p0 = sG1[0], p1 = sG2[0];
    float  cb = sCB[0];

    int last = count - 1;
    for (int i = 0; i < count; i++) {
        int j = min(i + 1, last);
        float4 n0 = sG1[j];
        float4 n1 = sG2[j];
        float  ncb = sCB[j];

        float dx  = px  - p0.x;
        float dy0 = py0 - p0.y;
        float dy1 = py1 - p0.y;
        float tx  = fmaf(p0.z, dx, p0.w * dy0);
        float ty  = fmaf(p0.w, dx, p1.x * dy0);
        float m0  = fmaf(tx, dx, ty * dy0);
        float ux  = fmaf(p0.z, dx, p0.w * dy1);
        float uy  = fmaf(p0.w, dx, p1.x * dy1);
        float m1  = fmaf(ux, dx, uy * dy1);

        if (fminf(m0, m1) < CUT) {
            float e0 = p1.y * __expf(-0.5f * m0);
            float e1 = p1.y * __expf(-0.5f * m1);
            float w0 = e0 * T0;
            float w1 = e1 * T1;
            aR0 = fmaf(w0, p1.z, aR0);
            aG0 = fmaf(w0, p1.w, aG0);
            aB0 = fmaf(w0, cb,   aB0);
            aR1 = fmaf(w1, p1.z, aR1);
            aG1 = fmaf(w1, p1.w, aG1);
            aB1 = fmaf(w1, cb,   aB1);
            T0 -= w0;
            T1 -= w1;
        }

        p0 = n0; p1 = n1; cb = ncb;
    }

    g_seg[oA] = make_float4(aR0, aG0, aB0, T0);
    g_seg[oB] = make_float4(aR1, aG1, aB1, T1);
}

// ---------------------------------------------------------------------------
// Merge: out = c0 + T0*(c1 + T1*(c2 + T2*c3)) per pixel.
// ---------------------------------------------------------------------------
__global__ void __launch_bounds__(256) merge_kernel(float* __restrict__ out) {
    int pix = blockIdx.x * 256 + threadIdx.x;
    float4 s0 = g_seg[pix];
    float4 s1 = g_seg[pix + NPIX];
    float4 s2 = g_seg[pix + 2 * NPIX];
    float4 s3 = g_seg[pix + 3 * NPIX];

    float R = fmaf(s2.w, s3.x, s2.x);
    float G = fmaf(s2.w, s3.y, s2.y);
    float B = fmaf(s2.w, s3.z, s2.z);
    R = fmaf(s1.w, R, s1.x);
    G = fmaf(s1.w, G, s1.y);
    B = fmaf(s1.w, B, s1.z);
    R = fmaf(s0.w, R, s0.x);
    G = fmaf(s0.w, G, s0.y);
    B = fmaf(s0.w, B, s0.z);

    int o = pix * 3;
    out[o + 0] = R;
    out[o + 1] = G;
    out[o + 2] = B;
}

extern "C" void kernel_launch(void* const* d_in, const int* in_sizes, int n_in,
                              void* d_out, int out_size) {
    const float* means3D   = (const float*)d_in[0];
    const float* covs3d    = (const float*)d_in[1];
    const float* colors    = (const float*)d_in[2];
    const float* opacities = (const float*)d_in[3];
    const float* K         = (const float*)d_in[4];
    const float* R         = (const float*)d_in[5];
    const float* t         = (const float*)d_in[6];
    float* out = (float*)d_out;

    project_kernel<<<32, 512>>>(means3D, covs3d, colors, opacities, K, R, t);

    dim3 grid(IMG_W / 32, IMG_H / 8, NSEG);
    render_kernel<<<grid, 128>>>();

    merge_kernel<<<NPIX / 256, 256>>>(out);
}